// round 16
// baseline (speedup 1.0000x reference)
#include <cuda_runtime.h>
#include <cuda_bf16.h>
#include <cstdint>

// Per molecule: S = 32x128 fp32, C = S S^T (32x32), output lambda_min(C).
// One warp per molecule:
//   1) Gram via cp.async-staged 32x32 chunks, SYMMETRIC diagonal-wrap
//      (t=0..16), packed f32x2 FMA; rows reconstructed via smem scatter.
//   2) Householder tridiagonalization, A-row in registers; cross-lane sums
//      via broadcast-LDS packed adds (no shfl butterflies), branchless.
//   3) lambda_min via 32-way multisection on the Sturm sequence (4 rounds).
//
// All shared-memory load wrappers are asm volatile with a "memory" clobber:
// without it the compiler may hoist them above the stores / cp.async.wait /
// __syncwarp they depend on (the R11/R12 correctness failure).

#define NA 32
#define NF 128
#define WPB 4   // warps (=molecules) per block

typedef unsigned long long u64;

__device__ __forceinline__ u64 pk2(float x, float y) {
    u64 r; asm("mov.b64 %0, {%1,%2};" : "=l"(r) : "f"(x), "f"(y)); return r;
}
__device__ __forceinline__ void upk2(u64 v, float& x, float& y) {
    asm("mov.b64 {%0,%1}, %2;" : "=f"(x), "=f"(y) : "l"(v));
}
__device__ __forceinline__ u64 ffma2(u64 a, u64 b, u64 c) {
    u64 d; asm("fma.rn.f32x2 %0, %1, %2, %3;" : "=l"(d) : "l"(a), "l"(b), "l"(c)); return d;
}
__device__ __forceinline__ u64 fadd2(u64 a, u64 b) {
    u64 d; asm("add.rn.f32x2 %0, %1, %2;" : "=l"(d) : "l"(a), "l"(b)); return d;
}
// ORDERED shared loads (volatile + memory clobber: may not cross stores/syncs)
__device__ __forceinline__ void lds_v2u64(uint32_t addr, u64& a, u64& b) {
    asm volatile("ld.shared.v2.b64 {%0,%1}, [%2];"
                 : "=l"(a), "=l"(b) : "r"(addr) : "memory");
}
__device__ __forceinline__ u64 lds_u64(uint32_t addr) {
    u64 a; asm volatile("ld.shared.b64 %0, [%1];" : "=l"(a) : "r"(addr) : "memory");
    return a;
}
__device__ __forceinline__ float lds_f32(uint32_t addr) {
    float a; asm volatile("ld.shared.f32 %0, [%1];" : "=f"(a) : "r"(addr) : "memory");
    return a;
}
__device__ __forceinline__ void sts_f32(uint32_t addr, float v) {
    asm volatile("st.shared.f32 [%0], %1;" :: "r"(addr), "f"(v) : "memory");
}
__device__ __forceinline__ void cp16(uint32_t dst, const void* src) {
    asm volatile("cp.async.ca.shared.global [%0], [%1], 16;" :: "r"(dst), "l"(src) : "memory");
}
// Sum of 32 contiguous f32 (128 bytes) in smem; broadcast loads -> all lanes
// get the same value. 8x LDS.128 + 15 fadd2 tree + final unpack add.
__device__ __forceinline__ float sum32(uint32_t base) {
    u64 a[16];
#pragma unroll
    for (int i = 0; i < 8; i++) lds_v2u64(base + i * 16, a[2 * i], a[2 * i + 1]);
    u64 s0 = fadd2(a[0],  a[1]),  s1 = fadd2(a[2],  a[3]);
    u64 s2 = fadd2(a[4],  a[5]),  s3 = fadd2(a[6],  a[7]);
    u64 s4 = fadd2(a[8],  a[9]),  s5 = fadd2(a[10], a[11]);
    u64 s6 = fadd2(a[12], a[13]), s7 = fadd2(a[14], a[15]);
    u64 t0 = fadd2(s0, s1), t1 = fadd2(s2, s3);
    u64 t2 = fadd2(s4, s5), t3 = fadd2(s6, s7);
    u64 t  = fadd2(fadd2(t0, t1), fadd2(t2, t3));
    float x, y; upk2(t, x, y);
    return x + y;
}

__global__ void __launch_bounds__(32 * WPB, 6)
corr_minEig_kernel(const float* __restrict__ S, float* __restrict__ out, int mtot) {
    // sS: 32x32 chunk staging (stride 36); reused post-Gram as C (stride 34)
    __shared__ __align__(16) float sS[WPB][NA * 36];
    __shared__ __align__(16) float sx2[WPB][NA];   // xr^2 (masked) for sigma sum
    __shared__ __align__(16) float svr[WPB][NA];   // raw v (x0 at k+1)
    __shared__ __align__(16) float svt[WPB][NA];   // true v (v0 at k+1)
    __shared__ __align__(16) float spv[WPB][NA];   // p*v terms
    __shared__ __align__(16) float sw[WPB][NA];    // Householder w
    __shared__ float sd[WPB][NA];                  // tridiagonal diag
    __shared__ float se2[WPB][NA];                 // tridiagonal offdiag^2

    const int w    = threadIdx.x >> 5;
    const int lane = threadIdx.x & 31;
    const int mol  = blockIdx.x * WPB + w;
    if (mol >= mtot) return;

    const float* Sm = S + (size_t)mol * NA * NF;
    const uint32_t sS_base  = (uint32_t)__cvta_generic_to_shared(&sS[w][0]);
    const uint32_t x2_base  = (uint32_t)__cvta_generic_to_shared(&sx2[w][0]);
    const uint32_t vr_base  = (uint32_t)__cvta_generic_to_shared(&svr[w][0]);
    const uint32_t vt_base  = (uint32_t)__cvta_generic_to_shared(&svt[w][0]);
    const uint32_t pv_base  = (uint32_t)__cvta_generic_to_shared(&spv[w][0]);
    const uint32_t w_base   = (uint32_t)__cvta_generic_to_shared(&sw[w][0]);
    float* d  = sd[w];
    float* e2 = se2[w];

    // ------------------------------------------------------------------
    // 1) Symmetric Gram: acc_t[t] = dot(row lane, row (lane+t)&31), t=0..16
    // ------------------------------------------------------------------
    float acc_t[17];
#pragma unroll
    for (int t = 0; t <= 16; t++) acc_t[t] = 0.f;

    for (int kc = 0; kc < NF; kc += 32) {
        // stage 32x32 chunk via cp.async (coalesced 128B segments)
#pragma unroll
        for (int it = 0; it < 8; it++) {
            int p   = it * 32 + lane;
            int row = p >> 3;
            int c4  = p & 7;
            cp16(sS_base + (uint32_t)(row * 36 + c4 * 4) * 4,
                 Sm + row * NF + kc + c4 * 4);
        }
        asm volatile("cp.async.commit_group;" ::: "memory");
        asm volatile("cp.async.wait_group 0;" ::: "memory");
        __syncwarp();

        // own row chunk -> 16 packed b64 (conflict-free)
        u64 a2[16];
#pragma unroll
        for (int c4 = 0; c4 < 8; c4++)
            lds_v2u64(sS_base + (uint32_t)(lane * 36 + c4 * 4) * 4, a2[2 * c4], a2[2 * c4 + 1]);

        // t = 0: self dot (no reload)
        {
            u64 s01 = 0, s23 = 0;
#pragma unroll
            for (int c4 = 0; c4 < 8; c4++) {
                s01 = ffma2(a2[2 * c4],     a2[2 * c4],     s01);
                s23 = ffma2(a2[2 * c4 + 1], a2[2 * c4 + 1], s23);
            }
            float lo, hi; upk2(fadd2(s01, s23), lo, hi);
            acc_t[0] += lo + hi;
        }
        // t = 1..16: rotated partner row (conflict-free at stride 36)
#pragma unroll
        for (int t = 1; t <= 16; t++) {
            int r = (lane + t) & 31;
            uint32_t raddr = sS_base + (uint32_t)r * 144u;
            u64 s01 = 0, s23 = 0;
#pragma unroll
            for (int c4 = 0; c4 < 8; c4++) {
                u64 b01, b23;
                lds_v2u64(raddr + c4 * 16u, b01, b23);
                s01 = ffma2(a2[2 * c4],     b01, s01);
                s23 = ffma2(a2[2 * c4 + 1], b23, s23);
            }
            float lo, hi; upk2(fadd2(s01, s23), lo, hi);
            acc_t[t] += lo + hi;
        }
        __syncwarp();
    }

    // Reconstruct full rows: scatter into C (stride 34, reusing sS space)
    float* C = sS[w];
#pragma unroll
    for (int t = 0; t <= 16; t++) {
        int j = (lane + t) & 31;
        C[lane * 34 + j] = acc_t[t];
        if (t != 0 && t != 16) C[j * 34 + lane] = acc_t[t];
    }
    __syncwarp();

    u64 arow[16];
#pragma unroll
    for (int i = 0; i < 16; i++)
        arow[i] = lds_u64(sS_base + (uint32_t)(lane * 34 + 2 * i) * 4);
    __syncwarp();

    // ------------------------------------------------------------------
    // 2) Householder tridiagonalization, fully unrolled, branchless,
    //    cross-lane sums via broadcast-LDS packed adds.
    // ------------------------------------------------------------------
#pragma unroll
    for (int k = 0; k < NA - 2; k++) {
        const int i0 = k >> 1;

        float ea, eb; upk2(arow[k >> 1], ea, eb);
        float xr = (k & 1) ? eb : ea;                    // A[lane][k] == A[k][lane]
        float xr2  = (lane > k + 1) ? xr * xr : 0.f;
        float vraw = (lane > k)     ? xr      : 0.f;     // x0 sits at slot k+1
        sts_f32(x2_base + lane * 4, xr2);
        sts_f32(vr_base + lane * 4, vraw);
        if (lane == k) d[k] = xr;                        // A[k][k] from own row
        __syncwarp();

        float sig = sum32(x2_base);
        float x0  = lds_f32(vr_base + (k + 1) * 4);      // broadcast
        float mu  = sqrtf(x0 * x0 + sig);
        float alpha = (x0 > 0.f) ? -mu : mu;
        float v0  = x0 - alpha;
        float beta = 2.f / fmaxf(v0 * v0 + sig, 1e-30f);
        if (lane == 0) e2[k + 1] = alpha * alpha;
        float vr = (lane == k + 1) ? v0 : vraw;

        // p_raw = A * v_raw; correct for v[k+1]: vtrue-vraw = -alpha there
        u64 p2a = 0, p2b = 0;
#pragma unroll
        for (int i = i0; i < 16; i += 2)
            p2a = ffma2(arow[i], lds_u64(vr_base + i * 8), p2a);
#pragma unroll
        for (int i = i0 + 1; i < 16; i += 2)
            p2b = ffma2(arow[i], lds_u64(vr_base + i * 8), p2b);
        float plo, phi; upk2(fadd2(p2a, p2b), plo, phi);
        float ca, cb; upk2(arow[(k + 1) >> 1], ca, cb);
        float a_k1 = ((k + 1) & 1) ? cb : ca;            // A[lane][k+1]
        float p = (plo + phi - alpha * a_k1) * beta;

        sts_f32(pv_base + lane * 4, p * vr);             // vr=0 for lane<=k
        sts_f32(vt_base + lane * 4, vr);
        __syncwarp();

        float s = sum32(pv_base);
        float K = 0.5f * beta * s;
        float wr = (lane > k) ? (p - K * vr) : 0.f;
        sts_f32(w_base + lane * 4, wr);
        __syncwarp();

        // A -= v w^T + w v^T (zero padding makes dead rows/cols no-ops)
        u64 nv = pk2(-vr, -vr);
        u64 nw = pk2(-wr, -wr);
#pragma unroll
        for (int i = i0; i < 16; i++) {
            u64 v2 = lds_u64(vt_base + i * 8);
            u64 w2 = lds_u64(w_base + i * 8);
            arow[i] = ffma2(nv, w2, ffma2(nw, v2, arow[i]));
        }
        __syncwarp();   // defensive: all lanes done with svt/sw before reuse
    }

    if (lane == NA - 2) {                 // row 30: pair 15 = (A[30][30], A[30][31])
        float a, b; upk2(arow[15], a, b);
        d[NA - 2] = a;
    }
    if (lane == NA - 1) {                 // row 31: pair 15 = (A[31][30], A[31][31])
        float a, b; upk2(arow[15], a, b);
        d[NA - 1] = b;
        e2[NA - 1] = a * a;
    }
    if (lane == 0) e2[0] = 0.f;
    __syncwarp();

    // ------------------------------------------------------------------
    // 3) lambda_min: Gershgorin bracket + 32-way multisection (Sturm count)
    // ------------------------------------------------------------------
    float ei  = sqrtf(e2[lane]);
    float eip = (lane < NA - 1) ? sqrtf(e2[lane + 1]) : 0.f;
    float rad = ei + eip;
    float dl  = d[lane];
    float lo = dl - rad, hi = dl + rad;
#pragma unroll
    for (int o = 16; o; o >>= 1) {
        lo = fminf(lo, __shfl_xor_sync(0xffffffffu, lo, o));
        hi = fmaxf(hi, __shfl_xor_sync(0xffffffffu, hi, o));
    }

    for (int it = 0; it < 4; it++) {
        float step = (hi - lo) * (1.f / 33.f);
        float x = lo + step * (float)(lane + 1);
        int cnt = 0;
        float q = d[0] - x;
        if (q < 0.f) cnt++;
#pragma unroll
        for (int i = 1; i < NA; i++) {
            if (fabsf(q) < 1e-25f) q = (q < 0.f) ? -1e-25f : 1e-25f;
            q = (d[i] - x) - __fdividef(e2[i], q);
            if (q < 0.f) cnt++;
        }
        unsigned mask = __ballot_sync(0xffffffffu, cnt >= 1);
        if (mask == 0u) {
            lo = lo + step * 32.f;
        } else {
            int idx = __ffs(mask) - 1;
            hi = lo + step * (float)(idx + 1);
            lo = lo + step * (float)idx;
        }
    }

    if (lane == 0) out[mol] = 0.5f * (lo + hi);
}

extern "C" void kernel_launch(void* const* d_in, const int* in_sizes, int n_in,
                              void* d_out, int out_size) {
    const float* sr = (const float*)d_in[0];   // [M*32, 128] fp32
    // d_in[1] = idx_m (int32) — uniform groups, unused
    float* out = (float*)d_out;

    int n_atoms = in_sizes[0] / NF;
    int mtot    = n_atoms / NA;

    int blocks = (mtot + WPB - 1) / WPB;
    corr_minEig_kernel<<<blocks, 32 * WPB>>>(sr, out, mtot);
}